// round 6
// baseline (speedup 1.0000x reference)
#include <cuda_runtime.h>
#include <math.h>

// Problem constants (fixed shapes from setup_inputs)
#define BATCH 8192
#define EXP   1024
#define RR    8
#define DIM   384
#define HID   64
#define KSEL  2
#define NP    (BATCH*KSEL)          // 16384 (b,k) pairs
#define TILE_S 32                   // score-tile rows (router-uniform)
#define TILE_X 16                   // xu/ev tile rows (smem limit)
#define LIST_CAP (NP + RR*TILE_S)   // 16640, padded-per-router upper bound
#define N_STILES (LIST_CAP/TILE_S)  // 520
#define N_XTILES (LIST_CAP/TILE_X)  // 1040

// ---------------- device scratch (static: no allocation allowed) ----------------
__device__ float g_probs[BATCH*RR];        // gate softmax probs (for aux)
__device__ int   g_top_idx[BATCH*KSEL];    // top-2 router ids
__device__ float g_top_gw[BATCH*KSEL];     // gate weights (softmax of top-2 logits)
__device__ int   g_cnt[RR];
__device__ int   g_pos[RR];
__device__ int   g_list_bk[LIST_CAP];      // b*2+k, -1 = sentinel
__device__ int   g_list_r[LIST_CAP];
__device__ float g_list_gw[LIST_CAP];
__device__ float g_xu[LIST_CAP*HID];       // l2norm(x@Uw+Ub) per list row
__device__ float g_ev[RR*EXP*HID];         // l2norm(re@Vw+Vb)
__device__ float g_contrib[NP*EXP];        // gate_weight * softmax(scores), per (b,k)

// ---------------- kernel 1: reset counters + sentinel list ----------------
__global__ void k_init() {
    int i = blockIdx.x * 256 + threadIdx.x;
    if (i < LIST_CAP) g_list_bk[i] = -1;
    if (i < RR) g_cnt[i] = 0;
}

// ---------------- kernel 2: gate (logits, probs, top-2, gate weights) ----------------
__global__ __launch_bounds__(256) void k_gate(const float* __restrict__ x,
                                              const float* __restrict__ gw,
                                              const float* __restrict__ gb) {
    int w = threadIdx.x >> 5, lane = threadIdx.x & 31;
    int b = blockIdx.x * 8 + w;
    float acc[8];
#pragma unroll
    for (int r = 0; r < 8; r++) acc[r] = 0.f;
    const float* xr = x + b * DIM;
    for (int k = lane; k < DIM; k += 32) {
        float xv = xr[k];
        float4 a = *(const float4*)(gw + k * 8);
        float4 c = *(const float4*)(gw + k * 8 + 4);
        acc[0] = fmaf(xv, a.x, acc[0]); acc[1] = fmaf(xv, a.y, acc[1]);
        acc[2] = fmaf(xv, a.z, acc[2]); acc[3] = fmaf(xv, a.w, acc[3]);
        acc[4] = fmaf(xv, c.x, acc[4]); acc[5] = fmaf(xv, c.y, acc[5]);
        acc[6] = fmaf(xv, c.z, acc[6]); acc[7] = fmaf(xv, c.w, acc[7]);
    }
#pragma unroll
    for (int r = 0; r < 8; r++)
#pragma unroll
        for (int s = 16; s; s >>= 1) acc[r] += __shfl_xor_sync(0xffffffffu, acc[r], s);
    if (lane == 0) {
        float lg[8];
#pragma unroll
        for (int r = 0; r < 8; r++) lg[r] = acc[r] + gb[r];
        // softmax over 8 (for aux loss)
        float m = lg[0];
#pragma unroll
        for (int r = 1; r < 8; r++) m = fmaxf(m, lg[r]);
        float s = 0.f, p[8];
#pragma unroll
        for (int r = 0; r < 8; r++) { p[r] = expf(lg[r] - m); s += p[r]; }
        float inv = 1.f / s;
#pragma unroll
        for (int r = 0; r < 8; r++) g_probs[b * 8 + r] = p[r] * inv;
        // top-2, stable (lowest index on tie, matching lax.top_k)
        int i0 = 0;
#pragma unroll
        for (int r = 1; r < 8; r++) if (lg[r] > lg[i0]) i0 = r;
        int i1 = (i0 == 0) ? 1 : 0;
#pragma unroll
        for (int r = 0; r < 8; r++) if (r != i0 && r != i1 && lg[r] > lg[i1]) i1 = r;
        float v0 = lg[i0], v1 = lg[i1];
        float e1 = expf(v1 - v0);           // v0 >= v1
        float d  = 1.f + e1;
        g_top_idx[b * 2 + 0] = i0; g_top_gw[b * 2 + 0] = 1.f / d;
        g_top_idx[b * 2 + 1] = i1; g_top_gw[b * 2 + 1] = e1 / d;
        atomicAdd(&g_cnt[i0], 1);
        atomicAdd(&g_cnt[i1], 1);
    }
}

// ---------------- kernel 3: padded bucket offsets (aligned to TILE_S) ----------------
__global__ void k_offsets() {
    int off = 0;
    for (int r = 0; r < RR; r++) {
        g_pos[r] = off;
        off += ((g_cnt[r] + TILE_S - 1) / TILE_S) * TILE_S;
    }
}

// ---------------- kernel 4: scatter (b,k) pairs into router-sorted list ----------------
__global__ void k_scatter() {
    int tid = blockIdx.x * 256 + threadIdx.x;   // tid = b*2+k
    if (tid < NP) {
        int r = g_top_idx[tid];
        int p = atomicAdd(&g_pos[r], 1);
        g_list_bk[p] = tid;
        g_list_r[p]  = r;
        g_list_gw[p] = g_top_gw[tid];
    }
}

// ---------------- kernel 5: xu = l2norm(x@Uw[r]+Ub[r]) per list row (router-uniform 16-row tiles) ----------------
__global__ __launch_bounds__(256) void k_xu(const float* __restrict__ x,
                                            const float* __restrict__ Uw,
                                            const float* __restrict__ Ub) {
    __shared__ float s_in[TILE_X * DIM];   // 24 KB
    __shared__ float s_w[64 * 64];         // 16 KB
    __shared__ int   s_bk[TILE_X];
    __shared__ int   sh_r;
    int t = threadIdx.x;
    int base = blockIdx.x * TILE_X;
    if (t < TILE_X) s_bk[t] = g_list_bk[base + t];
    if (t == 0) {
        int rr = 0;
        for (int i = 0; i < TILE_X; i++)
            if (g_list_bk[base + i] >= 0) { rr = g_list_r[base + i]; break; }
        sh_r = rr;
    }
    __syncthreads();
    int r = sh_r;
    // load 16 rows of x (zeros for sentinels)
#pragma unroll
    for (int i2 = 0; i2 < 6; i2++) {
        int f = t + 256 * i2;              // 0..1535 float4s
        int row = f / 96, q = f % 96;
        int bk = s_bk[row];
        float4 v = make_float4(0.f, 0.f, 0.f, 0.f);
        if (bk >= 0) v = *(const float4*)(x + (bk >> 1) * DIM + q * 4);
        *(float4*)&s_in[row * DIM + q * 4] = v;
    }
    int w = t >> 5, lane = t & 31;
    float a00 = 0.f, a01 = 0.f, a10 = 0.f, a11 = 0.f;
    const float* Wb = Uw + r * DIM * HID;
    for (int cc = 0; cc < 6; cc++) {
        __syncthreads();
#pragma unroll
        for (int i2 = 0; i2 < 4; i2++) {
            int f = t + 256 * i2;          // 0..1023 float4s
            *(float4*)&s_w[f * 4] = *(const float4*)(Wb + cc * 64 * 64 + f * 4);
        }
        __syncthreads();
        const float* xi0 = &s_in[(2 * w) * DIM + cc * 64];
        const float* xi1 = xi0 + DIM;
#pragma unroll 8
        for (int kk = 0; kk < 64; kk++) {
            float x0 = xi0[kk], x1 = xi1[kk];
            float w0 = s_w[kk * 64 + lane], w1 = s_w[kk * 64 + lane + 32];
            a00 = fmaf(x0, w0, a00); a01 = fmaf(x0, w1, a01);
            a10 = fmaf(x1, w0, a10); a11 = fmaf(x1, w1, a11);
        }
    }
    float b0 = Ub[r * HID + lane], b1 = Ub[r * HID + lane + 32];
    float y00 = a00 + b0, y01 = a01 + b1;
    float y10 = a10 + b0, y11 = a11 + b1;
    float ss0 = y00 * y00 + y01 * y01;
    float ss1 = y10 * y10 + y11 * y11;
#pragma unroll
    for (int s = 16; s; s >>= 1) {
        ss0 += __shfl_xor_sync(0xffffffffu, ss0, s);
        ss1 += __shfl_xor_sync(0xffffffffu, ss1, s);
    }
    float inv0 = 1.f / fmaxf(sqrtf(ss0), 1e-12f);
    float inv1 = 1.f / fmaxf(sqrtf(ss1), 1e-12f);
    float* o = g_xu + (base + 2 * w) * HID;
    o[lane]      = y00 * inv0; o[lane + 32] = y01 * inv0;
    o[64 + lane] = y10 * inv1; o[96 + lane] = y11 * inv1;
}

// ---------------- kernel 6: ev = l2norm(re@Vw[r]+Vb[r]) ----------------
__global__ __launch_bounds__(256) void k_ev(const float* __restrict__ re,
                                            const float* __restrict__ Vw,
                                            const float* __restrict__ Vb) {
    __shared__ float s_in[TILE_X * DIM];
    __shared__ float s_w[64 * 64];
    int t = threadIdx.x;
    int r  = blockIdx.x >> 6;              // 512 blocks: 64 tiles per router
    int e0 = (blockIdx.x & 63) * TILE_X;
#pragma unroll
    for (int i2 = 0; i2 < 6; i2++) {
        int f = t + 256 * i2;
        int row = f / 96, q = f % 96;
        *(float4*)&s_in[row * DIM + q * 4] = *(const float4*)(re + (e0 + row) * DIM + q * 4);
    }
    int w = t >> 5, lane = t & 31;
    float a00 = 0.f, a01 = 0.f, a10 = 0.f, a11 = 0.f;
    const float* Wb = Vw + r * DIM * HID;
    for (int cc = 0; cc < 6; cc++) {
        __syncthreads();
#pragma unroll
        for (int i2 = 0; i2 < 4; i2++) {
            int f = t + 256 * i2;
            *(float4*)&s_w[f * 4] = *(const float4*)(Wb + cc * 64 * 64 + f * 4);
        }
        __syncthreads();
        const float* xi0 = &s_in[(2 * w) * DIM + cc * 64];
        const float* xi1 = xi0 + DIM;
#pragma unroll 8
        for (int kk = 0; kk < 64; kk++) {
            float x0 = xi0[kk], x1 = xi1[kk];
            float w0 = s_w[kk * 64 + lane], w1 = s_w[kk * 64 + lane + 32];
            a00 = fmaf(x0, w0, a00); a01 = fmaf(x0, w1, a01);
            a10 = fmaf(x1, w0, a10); a11 = fmaf(x1, w1, a11);
        }
    }
    float b0 = Vb[r * HID + lane], b1 = Vb[r * HID + lane + 32];
    float y00 = a00 + b0, y01 = a01 + b1;
    float y10 = a10 + b0, y11 = a11 + b1;
    float ss0 = y00 * y00 + y01 * y01;
    float ss1 = y10 * y10 + y11 * y11;
#pragma unroll
    for (int s = 16; s; s >>= 1) {
        ss0 += __shfl_xor_sync(0xffffffffu, ss0, s);
        ss1 += __shfl_xor_sync(0xffffffffu, ss1, s);
    }
    float inv0 = 1.f / fmaxf(sqrtf(ss0), 1e-12f);
    float inv1 = 1.f / fmaxf(sqrtf(ss1), 1e-12f);
    float* o = g_ev + (r * EXP + e0 + 2 * w) * HID;
    o[lane]      = y00 * inv0; o[lane + 32] = y01 * inv0;
    o[64 + lane] = y10 * inv1; o[96 + lane] = y11 * inv1;
}

// ---------------- kernel 7: scores GEMM + softmax + gate-weight scale ----------------
// Tile = 32 router-uniform rows x 1024 experts, K=64. Warp w owns rows 4w..4w+3.
// Per kk: 4 broadcast xu LDS + 4 ev LDS feed 16 FFMA -> smem crossbar balanced
// with FFMA issue (the 2-row version was 1.5x crossbar-bound).
// ev staged via smem with stride-65 padding (conflict-free compute reads).
__global__ __launch_bounds__(256) void k_scores() {
    __shared__ float s_ev[128 * 65];       // 33.3 KB
    __shared__ float s_xu[TILE_S * HID];   // 8 KB
    __shared__ int   s_bk[TILE_S];
    __shared__ float s_gw[TILE_S];
    __shared__ int   sh_r;
    int t = threadIdx.x;
    int base = blockIdx.x * TILE_S;
    if (t < TILE_S) { s_bk[t] = g_list_bk[base + t]; s_gw[t] = g_list_gw[base + t]; }
    if (t == 0) {
        int rr = -1;
        for (int i = 0; i < TILE_S; i++)
            if (g_list_bk[base + i] >= 0) { rr = g_list_r[base + i]; break; }
        sh_r = rr;
    }
    __syncthreads();
    int r = sh_r;
    if (r < 0) return;                      // fully-sentinel tile (uniform across CTA)
    ((float4*)s_xu)[t]       = ((const float4*)(g_xu + base * HID))[t];
    ((float4*)s_xu)[t + 256] = ((const float4*)(g_xu + base * HID))[t + 256];

    int w = t >> 5, lane = t & 31;
    float sc[8][4][4];
#pragma unroll
    for (int c = 0; c < 8; c++)
#pragma unroll
        for (int i = 0; i < 4; i++)
#pragma unroll
            for (int j = 0; j < 4; j++) sc[c][i][j] = 0.f;

    const float* evb = g_ev + r * (EXP * HID);
#pragma unroll
    for (int c = 0; c < 8; c++) {
        __syncthreads();   // also covers s_xu on first iteration
#pragma unroll
        for (int i2 = 0; i2 < 8; i2++) {
            int f = t + 256 * i2;           // 0..2047 float4s
            int e = f >> 4, h4 = f & 15;
            float4 v = *(const float4*)(evb + (c * 128 + e) * HID + h4 * 4);
            float* d = &s_ev[e * 65 + h4 * 4];
            d[0] = v.x; d[1] = v.y; d[2] = v.z; d[3] = v.w;
        }
        __syncthreads();
        const float* xu0 = &s_xu[(4 * w) * HID];
#pragma unroll 4
        for (int kk = 0; kk < 64; kk++) {
            float x0 = xu0[kk];
            float x1 = xu0[HID + kk];
            float x2 = xu0[2 * HID + kk];
            float x3 = xu0[3 * HID + kk];
#pragma unroll
            for (int j = 0; j < 4; j++) {
                float e = s_ev[(j * 32 + lane) * 65 + kk];
                sc[c][0][j] = fmaf(x0, e, sc[c][0][j]);
                sc[c][1][j] = fmaf(x1, e, sc[c][1][j]);
                sc[c][2][j] = fmaf(x2, e, sc[c][2][j]);
                sc[c][3][j] = fmaf(x3, e, sc[c][3][j]);
            }
        }
    }
    // warp-local softmax per row, then scale by gate weight and write contribution
#pragma unroll
    for (int i = 0; i < 4; i++) {
        int row = 4 * w + i;
        float m = -1e30f;
#pragma unroll
        for (int c = 0; c < 8; c++)
#pragma unroll
            for (int j = 0; j < 4; j++) m = fmaxf(m, sc[c][i][j]);
#pragma unroll
        for (int s = 16; s; s >>= 1) m = fmaxf(m, __shfl_xor_sync(0xffffffffu, m, s));
        float sum = 0.f;
#pragma unroll
        for (int c = 0; c < 8; c++)
#pragma unroll
            for (int j = 0; j < 4; j++) {
                float ex = expf(sc[c][i][j] - m);
                sc[c][i][j] = ex;
                sum += ex;
            }
#pragma unroll
        for (int s = 16; s; s >>= 1) sum += __shfl_xor_sync(0xffffffffu, sum, s);
        int bk = s_bk[row];
        if (bk >= 0) {
            float scale = s_gw[row] / sum;
            float* out = g_contrib + bk * EXP;
#pragma unroll
            for (int c = 0; c < 8; c++)
#pragma unroll
                for (int j = 0; j < 4; j++)
                    out[c * 128 + j * 32 + lane] = sc[c][i][j] * scale;
        }
    }
}

// ---------------- kernel 8: aux loss (deterministic tree reduction) ----------------
__global__ __launch_bounds__(256) void k_aux(float* __restrict__ out) {
    __shared__ float sp[256][8];
    __shared__ float sm[256][8];
    int t = threadIdx.x;
    float p[8], mk[8];
#pragma unroll
    for (int r = 0; r < 8; r++) { p[r] = 0.f; mk[r] = 0.f; }
    for (int b = t; b < BATCH; b += 256) {
#pragma unroll
        for (int r = 0; r < 8; r++) p[r] += g_probs[b * 8 + r];
        int i0 = g_top_idx[b * 2], i1 = g_top_idx[b * 2 + 1];
#pragma unroll
        for (int r = 0; r < 8; r++) mk[r] += (r == i0 ? 1.f : 0.f) + (r == i1 ? 1.f : 0.f);
    }
#pragma unroll
    for (int r = 0; r < 8; r++) { sp[t][r] = p[r]; sm[t][r] = mk[r]; }
    __syncthreads();
    for (int s = 128; s; s >>= 1) {
        if (t < s)
#pragma unroll
            for (int r = 0; r < 8; r++) { sp[t][r] += sp[t + s][r]; sm[t][r] += sm[t + s][r]; }
        __syncthreads();
    }
    if (t == 0) {
        float a = 0.f;
#pragma unroll
        for (int r = 0; r < 8; r++)
            a += (sp[0][r] / (float)BATCH) * (sm[0][r] / (float)BATCH);
        out[2 * BATCH] = 8.f * a * 0.05f;
    }
}

// ---------------- kernel 9: inverse-CDF selection + log prob ----------------
__global__ __launch_bounds__(256) void k_select(const float* __restrict__ rnd,
                                                float* __restrict__ out) {
    int w = threadIdx.x >> 5, lane = threadIdx.x & 31;
    int b = blockIdx.x * 8 + w;
    float rn = rnd[b];
    const float* c0 = g_contrib + (b * 2) * EXP;
    const float* c1 = c0 + EXP;
    float run = 0.f;
    int sel = -1;
    for (int c = 0; c < 32; c++) {
        int e = c * 32 + lane;
        float v = c0[e] + c1[e];
        float s = v;
#pragma unroll
        for (int st = 1; st < 32; st <<= 1) {
            float o = __shfl_up_sync(0xffffffffu, s, st);
            if (lane >= st) s += o;
        }
        float cum = run + s;
        unsigned mask = __ballot_sync(0xffffffffu, cum > rn);
        if (mask) { sel = c * 32 + __ffs(mask) - 1; break; }
        run += __shfl_sync(0xffffffffu, s, 31);
    }
    if (sel < 0) sel = 0;                   // matches jnp.argmax of all-zero mask
    if (lane == 0) {
        float pv = c0[sel] + c1[sel];
        out[b] = (float)sel;
        out[BATCH + b] = logf(pv);
    }
}

// ---------------- launch ----------------
extern "C" void kernel_launch(void* const* d_in, const int* in_sizes, int n_in,
                              void* d_out, int out_size) {
    const float* x   = (const float*)d_in[0];  // [8192,384]
    const float* re  = (const float*)d_in[1];  // [1024,384]
    const float* rnd = (const float*)d_in[2];  // [8192,1]
    const float* gw  = (const float*)d_in[3];  // [384,8]
    const float* gb  = (const float*)d_in[4];  // [8]
    const float* Uw  = (const float*)d_in[5];  // [8,384,64]
    const float* Ub  = (const float*)d_in[6];  // [8,64]
    const float* Vw  = (const float*)d_in[7];  // [8,384,64]
    const float* Vb  = (const float*)d_in[8];  // [8,64]
    float* out = (float*)d_out;                // [0:8192]=idx, [8192:16384]=logp, [16384]=aux

    k_init   <<<(LIST_CAP + 255) / 256, 256>>>();
    k_gate   <<<BATCH / 8, 256>>>(x, gw, gb);
    k_offsets<<<1, 1>>>();
    k_scatter<<<NP / 256, 256>>>();
    k_ev     <<<RR * (EXP / TILE_X), 256>>>(re, Vw, Vb);
    k_xu     <<<N_XTILES, 256>>>(x, Uw, Ub);
    k_scores <<<N_STILES, 256>>>();
    k_aux    <<<1, 256>>>(out);
    k_select <<<BATCH / 8, 256>>>(rnd, out);
}

// round 7
// speedup vs baseline: 1.0022x; 1.0022x over previous
#include <cuda_runtime.h>
#include <math.h>

// Problem constants (fixed shapes from setup_inputs)
#define BATCH 8192
#define EXP   1024
#define RR    8
#define DIM   384
#define HID   64
#define KSEL  2
#define NP    (BATCH*KSEL)          // 16384 (b,k) pairs
#define TILE_S 32                   // score-tile rows (router-uniform)
#define TILE_X 16                   // xu/ev tile rows (smem limit)
#define LIST_CAP (NP + RR*TILE_S)   // 16640, padded-per-router upper bound
#define N_STILES (LIST_CAP/TILE_S)  // 520
#define N_XTILES (LIST_CAP/TILE_X)  // 1040

// ---------------- device scratch (static: no allocation allowed) ----------------
__device__ float g_probs[BATCH*RR];        // gate softmax probs (for aux)
__device__ int   g_top_idx[BATCH*KSEL];    // top-2 router ids
__device__ float g_top_gw[BATCH*KSEL];     // gate weights (softmax of top-2 logits)
__device__ int   g_cnt[RR];
__device__ int   g_pos[RR];
__device__ int   g_list_bk[LIST_CAP];      // b*2+k, -1 = sentinel
__device__ int   g_list_r[LIST_CAP];
__device__ float g_list_gw[LIST_CAP];
__device__ float g_xu[LIST_CAP*HID];       // l2norm(x@Uw+Ub) per list row
__device__ float g_ev[RR*EXP*HID];         // l2norm(re@Vw+Vb)
__device__ float g_contrib[NP*EXP];        // gate_weight * softmax(scores), per (b,k)

// ---------------- kernel 1: reset counters + sentinel list ----------------
__global__ void k_init() {
    int i = blockIdx.x * 256 + threadIdx.x;
    if (i < LIST_CAP) g_list_bk[i] = -1;
    if (i < RR) g_cnt[i] = 0;
}

// ---------------- kernel 2: gate (logits, probs, top-2, gate weights) ----------------
__global__ __launch_bounds__(256) void k_gate(const float* __restrict__ x,
                                              const float* __restrict__ gw,
                                              const float* __restrict__ gb) {
    int w = threadIdx.x >> 5, lane = threadIdx.x & 31;
    int b = blockIdx.x * 8 + w;
    float acc[8];
#pragma unroll
    for (int r = 0; r < 8; r++) acc[r] = 0.f;
    const float* xr = x + b * DIM;
    for (int k = lane; k < DIM; k += 32) {
        float xv = xr[k];
        float4 a = *(const float4*)(gw + k * 8);
        float4 c = *(const float4*)(gw + k * 8 + 4);
        acc[0] = fmaf(xv, a.x, acc[0]); acc[1] = fmaf(xv, a.y, acc[1]);
        acc[2] = fmaf(xv, a.z, acc[2]); acc[3] = fmaf(xv, a.w, acc[3]);
        acc[4] = fmaf(xv, c.x, acc[4]); acc[5] = fmaf(xv, c.y, acc[5]);
        acc[6] = fmaf(xv, c.z, acc[6]); acc[7] = fmaf(xv, c.w, acc[7]);
    }
#pragma unroll
    for (int r = 0; r < 8; r++)
#pragma unroll
        for (int s = 16; s; s >>= 1) acc[r] += __shfl_xor_sync(0xffffffffu, acc[r], s);
    if (lane == 0) {
        float lg[8];
#pragma unroll
        for (int r = 0; r < 8; r++) lg[r] = acc[r] + gb[r];
        // softmax over 8 (for aux loss)
        float m = lg[0];
#pragma unroll
        for (int r = 1; r < 8; r++) m = fmaxf(m, lg[r]);
        float s = 0.f, p[8];
#pragma unroll
        for (int r = 0; r < 8; r++) { p[r] = expf(lg[r] - m); s += p[r]; }
        float inv = 1.f / s;
#pragma unroll
        for (int r = 0; r < 8; r++) g_probs[b * 8 + r] = p[r] * inv;
        // top-2, stable (lowest index on tie, matching lax.top_k)
        int i0 = 0;
#pragma unroll
        for (int r = 1; r < 8; r++) if (lg[r] > lg[i0]) i0 = r;
        int i1 = (i0 == 0) ? 1 : 0;
#pragma unroll
        for (int r = 0; r < 8; r++) if (r != i0 && r != i1 && lg[r] > lg[i1]) i1 = r;
        float v0 = lg[i0], v1 = lg[i1];
        float e1 = expf(v1 - v0);           // v0 >= v1
        float d  = 1.f + e1;
        g_top_idx[b * 2 + 0] = i0; g_top_gw[b * 2 + 0] = 1.f / d;
        g_top_idx[b * 2 + 1] = i1; g_top_gw[b * 2 + 1] = e1 / d;
        atomicAdd(&g_cnt[i0], 1);
        atomicAdd(&g_cnt[i1], 1);
    }
}

// ---------------- kernel 3: padded bucket offsets (aligned to TILE_S) ----------------
__global__ void k_offsets() {
    int off = 0;
    for (int r = 0; r < RR; r++) {
        g_pos[r] = off;
        off += ((g_cnt[r] + TILE_S - 1) / TILE_S) * TILE_S;
    }
}

// ---------------- kernel 4: scatter (b,k) pairs into router-sorted list ----------------
__global__ void k_scatter() {
    int tid = blockIdx.x * 256 + threadIdx.x;   // tid = b*2+k
    if (tid < NP) {
        int r = g_top_idx[tid];
        int p = atomicAdd(&g_pos[r], 1);
        g_list_bk[p] = tid;
        g_list_r[p]  = r;
        g_list_gw[p] = g_top_gw[tid];
    }
}

// ---------------- kernel 5: xu = l2norm(x@Uw[r]+Ub[r]) per list row (router-uniform 16-row tiles) ----------------
__global__ __launch_bounds__(256) void k_xu(const float* __restrict__ x,
                                            const float* __restrict__ Uw,
                                            const float* __restrict__ Ub) {
    __shared__ float s_in[TILE_X * DIM];   // 24 KB
    __shared__ float s_w[64 * 64];         // 16 KB
    __shared__ int   s_bk[TILE_X];
    __shared__ int   sh_r;
    int t = threadIdx.x;
    int base = blockIdx.x * TILE_X;
    if (t < TILE_X) s_bk[t] = g_list_bk[base + t];
    if (t == 0) {
        int rr = 0;
        for (int i = 0; i < TILE_X; i++)
            if (g_list_bk[base + i] >= 0) { rr = g_list_r[base + i]; break; }
        sh_r = rr;
    }
    __syncthreads();
    int r = sh_r;
    // load 16 rows of x (zeros for sentinels)
#pragma unroll
    for (int i2 = 0; i2 < 6; i2++) {
        int f = t + 256 * i2;              // 0..1535 float4s
        int row = f / 96, q = f % 96;
        int bk = s_bk[row];
        float4 v = make_float4(0.f, 0.f, 0.f, 0.f);
        if (bk >= 0) v = *(const float4*)(x + (bk >> 1) * DIM + q * 4);
        *(float4*)&s_in[row * DIM + q * 4] = v;
    }
    int w = t >> 5, lane = t & 31;
    float a00 = 0.f, a01 = 0.f, a10 = 0.f, a11 = 0.f;
    const float* Wb = Uw + r * DIM * HID;
    for (int cc = 0; cc < 6; cc++) {
        __syncthreads();
#pragma unroll
        for (int i2 = 0; i2 < 4; i2++) {
            int f = t + 256 * i2;          // 0..1023 float4s
            *(float4*)&s_w[f * 4] = *(const float4*)(Wb + cc * 64 * 64 + f * 4);
        }
        __syncthreads();
        const float* xi0 = &s_in[(2 * w) * DIM + cc * 64];
        const float* xi1 = xi0 + DIM;
#pragma unroll 8
        for (int kk = 0; kk < 64; kk++) {
            float x0 = xi0[kk], x1 = xi1[kk];
            float w0 = s_w[kk * 64 + lane], w1 = s_w[kk * 64 + lane + 32];
            a00 = fmaf(x0, w0, a00); a01 = fmaf(x0, w1, a01);
            a10 = fmaf(x1, w0, a10); a11 = fmaf(x1, w1, a11);
        }
    }
    float b0 = Ub[r * HID + lane], b1 = Ub[r * HID + lane + 32];
    float y00 = a00 + b0, y01 = a01 + b1;
    float y10 = a10 + b0, y11 = a11 + b1;
    float ss0 = y00 * y00 + y01 * y01;
    float ss1 = y10 * y10 + y11 * y11;
#pragma unroll
    for (int s = 16; s; s >>= 1) {
        ss0 += __shfl_xor_sync(0xffffffffu, ss0, s);
        ss1 += __shfl_xor_sync(0xffffffffu, ss1, s);
    }
    float inv0 = 1.f / fmaxf(sqrtf(ss0), 1e-12f);
    float inv1 = 1.f / fmaxf(sqrtf(ss1), 1e-12f);
    float* o = g_xu + (base + 2 * w) * HID;
    o[lane]      = y00 * inv0; o[lane + 32] = y01 * inv0;
    o[64 + lane] = y10 * inv1; o[96 + lane] = y11 * inv1;
}

// ---------------- kernel 6: ev = l2norm(re@Vw[r]+Vb[r]) ----------------
__global__ __launch_bounds__(256) void k_ev(const float* __restrict__ re,
                                            const float* __restrict__ Vw,
                                            const float* __restrict__ Vb) {
    __shared__ float s_in[TILE_X * DIM];
    __shared__ float s_w[64 * 64];
    int t = threadIdx.x;
    int r  = blockIdx.x >> 6;              // 512 blocks: 64 tiles per router
    int e0 = (blockIdx.x & 63) * TILE_X;
#pragma unroll
    for (int i2 = 0; i2 < 6; i2++) {
        int f = t + 256 * i2;
        int row = f / 96, q = f % 96;
        *(float4*)&s_in[row * DIM + q * 4] = *(const float4*)(re + (e0 + row) * DIM + q * 4);
    }
    int w = t >> 5, lane = t & 31;
    float a00 = 0.f, a01 = 0.f, a10 = 0.f, a11 = 0.f;
    const float* Wb = Vw + r * DIM * HID;
    for (int cc = 0; cc < 6; cc++) {
        __syncthreads();
#pragma unroll
        for (int i2 = 0; i2 < 4; i2++) {
            int f = t + 256 * i2;
            *(float4*)&s_w[f * 4] = *(const float4*)(Wb + cc * 64 * 64 + f * 4);
        }
        __syncthreads();
        const float* xi0 = &s_in[(2 * w) * DIM + cc * 64];
        const float* xi1 = xi0 + DIM;
#pragma unroll 8
        for (int kk = 0; kk < 64; kk++) {
            float x0 = xi0[kk], x1 = xi1[kk];
            float w0 = s_w[kk * 64 + lane], w1 = s_w[kk * 64 + lane + 32];
            a00 = fmaf(x0, w0, a00); a01 = fmaf(x0, w1, a01);
            a10 = fmaf(x1, w0, a10); a11 = fmaf(x1, w1, a11);
        }
    }
    float b0 = Vb[r * HID + lane], b1 = Vb[r * HID + lane + 32];
    float y00 = a00 + b0, y01 = a01 + b1;
    float y10 = a10 + b0, y11 = a11 + b1;
    float ss0 = y00 * y00 + y01 * y01;
    float ss1 = y10 * y10 + y11 * y11;
#pragma unroll
    for (int s = 16; s; s >>= 1) {
        ss0 += __shfl_xor_sync(0xffffffffu, ss0, s);
        ss1 += __shfl_xor_sync(0xffffffffu, ss1, s);
    }
    float inv0 = 1.f / fmaxf(sqrtf(ss0), 1e-12f);
    float inv1 = 1.f / fmaxf(sqrtf(ss1), 1e-12f);
    float* o = g_ev + (r * EXP + e0 + 2 * w) * HID;
    o[lane]      = y00 * inv0; o[lane + 32] = y01 * inv0;
    o[64 + lane] = y10 * inv1; o[96 + lane] = y11 * inv1;
}

// ---------------- kernel 7: scores GEMM + softmax + gate-weight scale ----------------
// Tile = 32 router-uniform rows x 1024 experts, K=64. Warp w owns rows 4w..4w+3.
// Per kk: 4 broadcast xu LDS + 4 ev LDS feed 16 FFMA -> smem crossbar balanced
// with FFMA issue (the 2-row version was 1.5x crossbar-bound).
// ev staged via smem with stride-65 padding (conflict-free compute reads).
__global__ __launch_bounds__(256) void k_scores() {
    __shared__ float s_ev[128 * 65];       // 33.3 KB
    __shared__ float s_xu[TILE_S * HID];   // 8 KB
    __shared__ int   s_bk[TILE_S];
    __shared__ float s_gw[TILE_S];
    __shared__ int   sh_r;
    int t = threadIdx.x;
    int base = blockIdx.x * TILE_S;
    if (t < TILE_S) { s_bk[t] = g_list_bk[base + t]; s_gw[t] = g_list_gw[base + t]; }
    if (t == 0) {
        int rr = -1;
        for (int i = 0; i < TILE_S; i++)
            if (g_list_bk[base + i] >= 0) { rr = g_list_r[base + i]; break; }
        sh_r = rr;
    }
    __syncthreads();
    int r = sh_r;
    if (r < 0) return;                      // fully-sentinel tile (uniform across CTA)
    ((float4*)s_xu)[t]       = ((const float4*)(g_xu + base * HID))[t];
    ((float4*)s_xu)[t + 256] = ((const float4*)(g_xu + base * HID))[t + 256];

    int w = t >> 5, lane = t & 31;
    float sc[8][4][4];
#pragma unroll
    for (int c = 0; c < 8; c++)
#pragma unroll
        for (int i = 0; i < 4; i++)
#pragma unroll
            for (int j = 0; j < 4; j++) sc[c][i][j] = 0.f;

    const float* evb = g_ev + r * (EXP * HID);
#pragma unroll
    for (int c = 0; c < 8; c++) {
        __syncthreads();   // also covers s_xu on first iteration
#pragma unroll
        for (int i2 = 0; i2 < 8; i2++) {
            int f = t + 256 * i2;           // 0..2047 float4s
            int e = f >> 4, h4 = f & 15;
            float4 v = *(const float4*)(evb + (c * 128 + e) * HID + h4 * 4);
            float* d = &s_ev[e * 65 + h4 * 4];
            d[0] = v.x; d[1] = v.y; d[2] = v.z; d[3] = v.w;
        }
        __syncthreads();
        const float* xu0 = &s_xu[(4 * w) * HID];
#pragma unroll 4
        for (int kk = 0; kk < 64; kk++) {
            float x0 = xu0[kk];
            float x1 = xu0[HID + kk];
            float x2 = xu0[2 * HID + kk];
            float x3 = xu0[3 * HID + kk];
#pragma unroll
            for (int j = 0; j < 4; j++) {
                float e = s_ev[(j * 32 + lane) * 65 + kk];
                sc[c][0][j] = fmaf(x0, e, sc[c][0][j]);
                sc[c][1][j] = fmaf(x1, e, sc[c][1][j]);
                sc[c][2][j] = fmaf(x2, e, sc[c][2][j]);
                sc[c][3][j] = fmaf(x3, e, sc[c][3][j]);
            }
        }
    }
    // warp-local softmax per row, then scale by gate weight and write contribution
#pragma unroll
    for (int i = 0; i < 4; i++) {
        int row = 4 * w + i;
        float m = -1e30f;
#pragma unroll
        for (int c = 0; c < 8; c++)
#pragma unroll
            for (int j = 0; j < 4; j++) m = fmaxf(m, sc[c][i][j]);
#pragma unroll
        for (int s = 16; s; s >>= 1) m = fmaxf(m, __shfl_xor_sync(0xffffffffu, m, s));
        float sum = 0.f;
#pragma unroll
        for (int c = 0; c < 8; c++)
#pragma unroll
            for (int j = 0; j < 4; j++) {
                float ex = expf(sc[c][i][j] - m);
                sc[c][i][j] = ex;
                sum += ex;
            }
#pragma unroll
        for (int s = 16; s; s >>= 1) sum += __shfl_xor_sync(0xffffffffu, sum, s);
        int bk = s_bk[row];
        if (bk >= 0) {
            float scale = s_gw[row] / sum;
            float* out = g_contrib + bk * EXP;
#pragma unroll
            for (int c = 0; c < 8; c++)
#pragma unroll
                for (int j = 0; j < 4; j++)
                    out[c * 128 + j * 32 + lane] = sc[c][i][j] * scale;
        }
    }
}

// ---------------- kernel 8: aux loss (deterministic tree reduction) ----------------
__global__ __launch_bounds__(256) void k_aux(float* __restrict__ out) {
    __shared__ float sp[256][8];
    __shared__ float sm[256][8];
    int t = threadIdx.x;
    float p[8], mk[8];
#pragma unroll
    for (int r = 0; r < 8; r++) { p[r] = 0.f; mk[r] = 0.f; }
    for (int b = t; b < BATCH; b += 256) {
#pragma unroll
        for (int r = 0; r < 8; r++) p[r] += g_probs[b * 8 + r];
        int i0 = g_top_idx[b * 2], i1 = g_top_idx[b * 2 + 1];
#pragma unroll
        for (int r = 0; r < 8; r++) mk[r] += (r == i0 ? 1.f : 0.f) + (r == i1 ? 1.f : 0.f);
    }
#pragma unroll
    for (int r = 0; r < 8; r++) { sp[t][r] = p[r]; sm[t][r] = mk[r]; }
    __syncthreads();
    for (int s = 128; s; s >>= 1) {
        if (t < s)
#pragma unroll
            for (int r = 0; r < 8; r++) { sp[t][r] += sp[t + s][r]; sm[t][r] += sm[t + s][r]; }
        __syncthreads();
    }
    if (t == 0) {
        float a = 0.f;
#pragma unroll
        for (int r = 0; r < 8; r++)
            a += (sp[0][r] / (float)BATCH) * (sm[0][r] / (float)BATCH);
        out[2 * BATCH] = 8.f * a * 0.05f;
    }
}

// ---------------- kernel 9: inverse-CDF selection + log prob ----------------
__global__ __launch_bounds__(256) void k_select(const float* __restrict__ rnd,
                                                float* __restrict__ out) {
    int w = threadIdx.x >> 5, lane = threadIdx.x & 31;
    int b = blockIdx.x * 8 + w;
    float rn = rnd[b];
    const float* c0 = g_contrib + (b * 2) * EXP;
    const float* c1 = c0 + EXP;
    float run = 0.f;
    int sel = -1;
    for (int c = 0; c < 32; c++) {
        int e = c * 32 + lane;
        float v = c0[e] + c1[e];
        float s = v;
#pragma unroll
        for (int st = 1; st < 32; st <<= 1) {
            float o = __shfl_up_sync(0xffffffffu, s, st);
            if (lane >= st) s += o;
        }
        float cum = run + s;
        unsigned mask = __ballot_sync(0xffffffffu, cum > rn);
        if (mask) { sel = c * 32 + __ffs(mask) - 1; break; }
        run += __shfl_sync(0xffffffffu, s, 31);
    }
    if (sel < 0) sel = 0;                   // matches jnp.argmax of all-zero mask
    if (lane == 0) {
        float pv = c0[sel] + c1[sel];
        out[b] = (float)sel;
        out[BATCH + b] = logf(pv);
    }
}

// ---------------- launch ----------------
extern "C" void kernel_launch(void* const* d_in, const int* in_sizes, int n_in,
                              void* d_out, int out_size) {
    const float* x   = (const float*)d_in[0];  // [8192,384]
    const float* re  = (const float*)d_in[1];  // [1024,384]
    const float* rnd = (const float*)d_in[2];  // [8192,1]
    const float* gw  = (const float*)d_in[3];  // [384,8]
    const float* gb  = (const float*)d_in[4];  // [8]
    const float* Uw  = (const float*)d_in[5];  // [8,384,64]
    const float* Ub  = (const float*)d_in[6];  // [8,64]
    const float* Vw  = (const float*)d_in[7];  // [8,384,64]
    const float* Vb  = (const float*)d_in[8];  // [8,64]
    float* out = (float*)d_out;                // [0:8192]=idx, [8192:16384]=logp, [16384]=aux

    k_init   <<<(LIST_CAP + 255) / 256, 256>>>();
    k_gate   <<<BATCH / 8, 256>>>(x, gw, gb);
    k_offsets<<<1, 1>>>();
    k_scatter<<<NP / 256, 256>>>();
    k_ev     <<<RR * (EXP / TILE_X), 256>>>(re, Vw, Vb);
    k_xu     <<<N_XTILES, 256>>>(x, Uw, Ub);
    k_scores <<<N_STILES, 256>>>();
    k_aux    <<<1, 256>>>(out);
    k_select <<<BATCH / 8, 256>>>(rnd, out);
}

// round 8
// speedup vs baseline: 1.3122x; 1.3093x over previous
#include <cuda_runtime.h>
#include <math.h>

#define BATCH 8192
#define EXP   1024
#define RR    8
#define DIM   384
#define HID   64
#define NP    (BATCH*2)             // 16384 (b,k) pairs
#define TILE  64                    // rows per tile (router-uniform)
#define LIST_CAP (NP + RR*TILE)     // 16896
#define N_TILES (LIST_CAP/TILE)     // 264

typedef unsigned long long u64;

// ---------------- f32x2 helpers (sm_103a packed fp32: 2x FMA throughput) ----------------
__device__ __forceinline__ u64 pack2(float lo, float hi) {
    u64 r; asm("mov.b64 %0, {%1, %2};" : "=l"(r) : "f"(lo), "f"(hi)); return r;
}
__device__ __forceinline__ float2 unpack2(u64 v) {
    float2 f; asm("mov.b64 {%0, %1}, %2;" : "=f"(f.x), "=f"(f.y) : "l"(v)); return f;
}
__device__ __forceinline__ void fma2(u64& d, u64 a, u64 b) {
    asm("fma.rn.f32x2 %0, %1, %2, %0;" : "+l"(d) : "l"(a), "l"(b));
}

// ---------------- device scratch ----------------
__device__ __align__(16) float g_probs[BATCH*RR];
__device__ int   g_top_idx[NP];
__device__ float g_top_gw[NP];
__device__ int   g_cnt[RR];
__device__ int   g_pos[RR];
__device__ int   g_list_bk[LIST_CAP];       // b*2+k, -1 = sentinel
__device__ float g_list_gw[LIST_CAP];
__device__ int   g_tile_r[N_TILES];         // router per 64-row tile, -1 = unused
__device__ __align__(16) float g_xu[LIST_CAP*HID];   // natural [row][h]
__device__ __align__(16) float g_ev[RR*EXP*HID];     // natural [r][e][h]
__device__ __align__(16) float g_contrib[NP*EXP];    // UNSCALED exp(score)
__device__ float g_scale[NP];               // gate_weight / sum_exp

// ---------------- kernel 1: init ----------------
__global__ void k_init() {
    int i = blockIdx.x * 256 + threadIdx.x;
    if (i < LIST_CAP) g_list_bk[i] = -1;
    if (i < N_TILES)  g_tile_r[i] = -1;
    if (i < RR)       g_cnt[i] = 0;
}

// ---------------- kernel 2: gate ----------------
__global__ __launch_bounds__(256) void k_gate(const float* __restrict__ x,
                                              const float* __restrict__ gw,
                                              const float* __restrict__ gb) {
    int w = threadIdx.x >> 5, lane = threadIdx.x & 31;
    int b = blockIdx.x * 8 + w;
    float acc[8];
#pragma unroll
    for (int r = 0; r < 8; r++) acc[r] = 0.f;
    const float* xr = x + b * DIM;
    for (int k = lane; k < DIM; k += 32) {
        float xv = xr[k];
        float4 a = *(const float4*)(gw + k * 8);
        float4 c = *(const float4*)(gw + k * 8 + 4);
        acc[0] = fmaf(xv, a.x, acc[0]); acc[1] = fmaf(xv, a.y, acc[1]);
        acc[2] = fmaf(xv, a.z, acc[2]); acc[3] = fmaf(xv, a.w, acc[3]);
        acc[4] = fmaf(xv, c.x, acc[4]); acc[5] = fmaf(xv, c.y, acc[5]);
        acc[6] = fmaf(xv, c.z, acc[6]); acc[7] = fmaf(xv, c.w, acc[7]);
    }
#pragma unroll
    for (int r = 0; r < 8; r++)
#pragma unroll
        for (int s = 16; s; s >>= 1) acc[r] += __shfl_xor_sync(0xffffffffu, acc[r], s);
    if (lane == 0) {
        float lg[8];
#pragma unroll
        for (int r = 0; r < 8; r++) lg[r] = acc[r] + gb[r];
        float m = lg[0];
#pragma unroll
        for (int r = 1; r < 8; r++) m = fmaxf(m, lg[r]);
        float s = 0.f, p[8];
#pragma unroll
        for (int r = 0; r < 8; r++) { p[r] = expf(lg[r] - m); s += p[r]; }
        float inv = 1.f / s;
#pragma unroll
        for (int r = 0; r < 8; r++) g_probs[b * 8 + r] = p[r] * inv;
        int i0 = 0;
#pragma unroll
        for (int r = 1; r < 8; r++) if (lg[r] > lg[i0]) i0 = r;
        int i1 = (i0 == 0) ? 1 : 0;
#pragma unroll
        for (int r = 0; r < 8; r++) if (r != i0 && r != i1 && lg[r] > lg[i1]) i1 = r;
        float e1 = expf(lg[i1] - lg[i0]);   // lg[i0] >= lg[i1]
        float d  = 1.f + e1;
        g_top_idx[b * 2 + 0] = i0; g_top_gw[b * 2 + 0] = 1.f / d;
        g_top_idx[b * 2 + 1] = i1; g_top_gw[b * 2 + 1] = e1 / d;
        atomicAdd(&g_cnt[i0], 1);
        atomicAdd(&g_cnt[i1], 1);
    }
}

// ---------------- kernel 3: padded bucket offsets + tile routers ----------------
__global__ void k_offsets() {
    int off = 0;
    for (int r = 0; r < RR; r++) {
        g_pos[r] = off;
        int pad = ((g_cnt[r] + TILE - 1) / TILE) * TILE;
        for (int tl = off / TILE; tl < (off + pad) / TILE; tl++) g_tile_r[tl] = r;
        off += pad;
    }
}

// ---------------- kernel 4: scatter (warp-aggregated atomics) ----------------
__global__ void k_scatter() {
    int tid = blockIdx.x * 256 + threadIdx.x;   // tid = b*2+k
    int lane = threadIdx.x & 31;
    int r = g_top_idx[tid];
    int p = 0;
#pragma unroll
    for (int rr = 0; rr < RR; rr++) {
        unsigned m = __ballot_sync(0xffffffffu, r == rr);
        if (r == rr) {
            int leader = __ffs(m) - 1;
            int basep = 0;
            if (lane == leader) basep = atomicAdd(&g_pos[rr], __popc(m));
            basep = __shfl_sync(m, basep, leader);
            p = basep + __popc(m & ((1u << lane) - 1u));
        }
    }
    g_list_bk[p] = tid;
    g_list_gw[p] = g_top_gw[tid];
}

// ---------------- shared GEMM body for xu/ev: 64 rows x 64 hid, K=384, f32x2 over d ----
// warp w owns rows 8w..8w+7; lane owns hid pair {lane, lane+32}.
// s_w: u64-swizzled [h][d2]: slot = h*32 + (d2 ^ (h&31)).
template<bool IS_XU>
__device__ __forceinline__ void proj_body(const float* __restrict__ src,
                                          const float* __restrict__ Wb,
                                          const float* __restrict__ bias,
                                          const int* s_bk, int base, int e0,
                                          float* s_in, u64* s_w,
                                          float* dst) {
    int t = threadIdx.x, w = t >> 5, lane = t & 31;
    u64 acc[8][2];
#pragma unroll
    for (int i = 0; i < 8; i++) { acc[i][0] = 0ull; acc[i][1] = 0ull; }
    for (int c = 0; c < 6; c++) {
        __syncthreads();
#pragma unroll
        for (int i = 0; i < 4; i++) {          // stage 64 rows x 64 d (natural)
            int f = t + 256 * i, row = f >> 4, d16 = f & 15;
            float4 v = make_float4(0.f, 0.f, 0.f, 0.f);
            if (IS_XU) {
                int bk = s_bk[row];
                if (bk >= 0) v = *(const float4*)(src + (bk >> 1) * DIM + c * 64 + d16 * 4);
            } else {
                v = *(const float4*)(src + (e0 + row) * DIM + c * 64 + d16 * 4);
            }
            *(float4*)&s_in[row * 64 + d16 * 4] = v;
        }
        float* sw = (float*)s_w;
#pragma unroll
        for (int i = 0; i < 4; i++) {          // stage weights: transpose + swizzle
            int f = t + 256 * i, d = f >> 4, h16 = f & 15;
            float4 v = *(const float4*)(Wb + (c * 64 + d) * HID + h16 * 4);
            int d2 = d >> 1, par = d & 1;
            float vv[4] = {v.x, v.y, v.z, v.w};
#pragma unroll
            for (int jj = 0; jj < 4; jj++) {
                int h = h16 * 4 + jj;
                sw[(h * 32 + (d2 ^ (h & 31))) * 2 + par] = vv[jj];
            }
        }
        __syncthreads();
#pragma unroll 4
        for (int d2 = 0; d2 < 32; d2++) {
            u64 w0 = s_w[lane * 32 + (d2 ^ lane)];
            u64 w1 = s_w[(lane + 32) * 32 + (d2 ^ lane)];
#pragma unroll
            for (int i = 0; i < 8; i++) {
                u64 xv = *(const u64*)&s_in[(8 * w + i) * 64 + 2 * d2]; // broadcast
                fma2(acc[i][0], xv, w0);
                fma2(acc[i][1], xv, w1);
            }
        }
    }
    float b0 = bias[lane], b1 = bias[lane + 32];
#pragma unroll
    for (int i = 0; i < 8; i++) {
        float2 p0 = unpack2(acc[i][0]), p1 = unpack2(acc[i][1]);
        float y0 = p0.x + p0.y + b0;
        float y1 = p1.x + p1.y + b1;
        float ss = y0 * y0 + y1 * y1;
#pragma unroll
        for (int s = 16; s; s >>= 1) ss += __shfl_xor_sync(0xffffffffu, ss, s);
        float inv = 1.f / fmaxf(sqrtf(ss), 1e-12f);
        int row = base + 8 * w + i;
        dst[row * HID + lane]      = y0 * inv;
        dst[row * HID + lane + 32] = y1 * inv;
    }
}

__global__ __launch_bounds__(256) void k_xu(const float* __restrict__ x,
                                            const float* __restrict__ Uw,
                                            const float* __restrict__ Ub) {
    __shared__ float s_in[64 * 64];
    __shared__ u64   s_w[64 * 32];
    __shared__ int   s_bk[64];
    int t = threadIdx.x;
    int tile = blockIdx.x;
    int r = g_tile_r[tile];
    if (r < 0) return;
    int base = tile * TILE;
    if (t < 64) s_bk[t] = g_list_bk[base + t];
    proj_body<true>(x, Uw + r * DIM * HID, Ub + r * HID, s_bk, base, 0, s_in, s_w, g_xu);
}

__global__ __launch_bounds__(256) void k_ev(const float* __restrict__ re,
                                            const float* __restrict__ Vw,
                                            const float* __restrict__ Vb) {
    __shared__ float s_in[64 * 64];
    __shared__ u64   s_w[64 * 32];
    int r  = blockIdx.x >> 4;               // 128 blocks: 16 tiles per router
    int e0 = (blockIdx.x & 15) * 64;
    proj_body<false>(re, Vw + r * DIM * HID, Vb + r * HID, 0, r * EXP + e0, e0,
                     s_in, s_w, g_ev);
}

// ---------------- kernel 7: scores GEMM + exp + per-row sum ----------------
// 64-row tile x 1024 experts, 8 chunks of 128 experts. warp w: rows 8w..8w+7;
// lane covers experts {lane, +32, +64, +96} per chunk. kk-packed f32x2.
// ev XOR-swizzled in u64 units -> clean 2-phase LDS.64; xu rows via LDS.64 broadcast.
// Per CTA per kk-pair: 128 crossbar phases == 128 FFMA2-cycles (balanced).
__global__ __launch_bounds__(256) void k_scores() {
    extern __shared__ u64 dyn[];
    u64*   s_ev = dyn;                      // 4096 u64 = 32 KB
    float* s_xu = (float*)(dyn + 4096);     // 16 KB
    __shared__ int   s_bk[64];
    __shared__ float s_gw[64];
    int t = threadIdx.x, w = t >> 5, lane = t & 31;
    int tile = blockIdx.x;
    int r = g_tile_r[tile];
    if (r < 0) return;
    int base = tile * TILE;
    if (t < 64) { s_bk[t] = g_list_bk[base + t]; s_gw[t] = g_list_gw[base + t]; }
#pragma unroll
    for (int i = 0; i < 4; i++)
        ((float4*)s_xu)[t + 256 * i] = ((const float4*)(g_xu + base * HID))[t + 256 * i];

    float rowsum[8];
#pragma unroll
    for (int i = 0; i < 8; i++) rowsum[i] = 0.f;

    const float* evb = g_ev + r * (EXP * HID);
    for (int c = 0; c < 8; c++) {
        __syncthreads();                    // covers s_xu/s_bk first iter, s_ev reuse later
#pragma unroll
        for (int i = 0; i < 8; i++) {       // stage 128 experts x 64 h, swizzled pairs
            int f = t + 256 * i, e = f >> 4, k4 = f & 15;
            float4 v = *(const float4*)(evb + (c * 128 + e) * HID + k4 * 4);
            int s = e & 31;
            s_ev[e * 32 + ((2 * k4) ^ s)]     = pack2(v.x, v.y);
            s_ev[e * 32 + ((2 * k4 + 1) ^ s)] = pack2(v.z, v.w);
        }
        __syncthreads();
        u64 acc[8][4];
#pragma unroll
        for (int i = 0; i < 8; i++)
#pragma unroll
            for (int j = 0; j < 4; j++) acc[i][j] = 0ull;
#pragma unroll 4
        for (int kk2 = 0; kk2 < 32; kk2++) {
            int sw = kk2 ^ lane;
            u64 e0 = s_ev[lane * 32 + sw];
            u64 e1 = s_ev[(lane + 32) * 32 + sw];
            u64 e2 = s_ev[(lane + 64) * 32 + sw];
            u64 e3 = s_ev[(lane + 96) * 32 + sw];
#pragma unroll
            for (int i = 0; i < 8; i++) {
                u64 xv = *(const u64*)&s_xu[(8 * w + i) * 64 + 2 * kk2]; // broadcast
                fma2(acc[i][0], xv, e0);
                fma2(acc[i][1], xv, e1);
                fma2(acc[i][2], xv, e2);
                fma2(acc[i][3], xv, e3);
            }
        }
        // per-chunk epilogue: exp (|score|<=1, no max needed), unscaled write, run sums
#pragma unroll
        for (int i = 0; i < 8; i++) {
            int bk = s_bk[8 * w + i];
            float ex[4], loc = 0.f;
#pragma unroll
            for (int j = 0; j < 4; j++) {
                float2 p = unpack2(acc[i][j]);
                ex[j] = __expf(p.x + p.y);
                loc += ex[j];
            }
            rowsum[i] += loc;
            if (bk >= 0) {
                float* o = g_contrib + bk * EXP + c * 128;
#pragma unroll
                for (int j = 0; j < 4; j++) o[j * 32 + lane] = ex[j];
            }
        }
    }
#pragma unroll
    for (int i = 0; i < 8; i++) {
        float s = rowsum[i];
#pragma unroll
        for (int st = 16; st; st >>= 1) s += __shfl_xor_sync(0xffffffffu, s, st);
        int row = 8 * w + i;
        int bk = s_bk[row];
        if (lane == 0 && bk >= 0) g_scale[bk] = s_gw[row] / s;
    }
}

// ---------------- kernel 8: aux loss ----------------
__global__ __launch_bounds__(256) void k_aux(float* __restrict__ out) {
    __shared__ float sp[256][8];
    __shared__ float sm[256][8];
    int t = threadIdx.x;
    float p[8], mk[8];
#pragma unroll
    for (int r = 0; r < 8; r++) { p[r] = 0.f; mk[r] = 0.f; }
    for (int b = t; b < BATCH; b += 256) {
#pragma unroll
        for (int r = 0; r < 8; r++) p[r] += g_probs[b * 8 + r];
        int i0 = g_top_idx[b * 2], i1 = g_top_idx[b * 2 + 1];
#pragma unroll
        for (int r = 0; r < 8; r++) mk[r] += (r == i0 ? 1.f : 0.f) + (r == i1 ? 1.f : 0.f);
    }
#pragma unroll
    for (int r = 0; r < 8; r++) { sp[t][r] = p[r]; sm[t][r] = mk[r]; }
    __syncthreads();
    for (int s = 128; s; s >>= 1) {
        if (t < s)
#pragma unroll
            for (int r = 0; r < 8; r++) { sp[t][r] += sp[t + s][r]; sm[t][r] += sm[t + s][r]; }
        __syncthreads();
    }
    if (t == 0) {
        float a = 0.f;
#pragma unroll
        for (int r = 0; r < 8; r++)
            a += (sp[0][r] / (float)BATCH) * (sm[0][r] / (float)BATCH);
        out[2 * BATCH] = 8.f * a * 0.05f;
    }
}

// ---------------- kernel 9: inverse-CDF selection (applies per-(b,k) scales) ----------
__global__ __launch_bounds__(256) void k_select(const float* __restrict__ rnd,
                                                float* __restrict__ out) {
    int w = threadIdx.x >> 5, lane = threadIdx.x & 31;
    int b = blockIdx.x * 8 + w;
    float rn = rnd[b];
    float s0 = g_scale[b * 2], s1 = g_scale[b * 2 + 1];
    const float* c0 = g_contrib + (b * 2) * EXP;
    const float* c1 = c0 + EXP;
    float run = 0.f;
    int sel = -1;
    for (int c = 0; c < 32; c++) {
        int e = c * 32 + lane;
        float v = c0[e] * s0 + c1[e] * s1;
        float s = v;
#pragma unroll
        for (int st = 1; st < 32; st <<= 1) {
            float o = __shfl_up_sync(0xffffffffu, s, st);
            if (lane >= st) s += o;
        }
        float cum = run + s;
        unsigned mask = __ballot_sync(0xffffffffu, cum > rn);
        if (mask) { sel = c * 32 + __ffs(mask) - 1; break; }
        run += __shfl_sync(0xffffffffu, s, 31);
    }
    if (sel < 0) sel = 0;
    if (lane == 0) {
        float pv = c0[sel] * s0 + c1[sel] * s1;
        out[b] = (float)sel;
        out[BATCH + b] = logf(pv);
    }
}

// ---------------- launch ----------------
extern "C" void kernel_launch(void* const* d_in, const int* in_sizes, int n_in,
                              void* d_out, int out_size) {
    const float* x   = (const float*)d_in[0];  // [8192,384]
    const float* re  = (const float*)d_in[1];  // [1024,384]
    const float* rnd = (const float*)d_in[2];  // [8192,1]
    const float* gw  = (const float*)d_in[3];  // [384,8]
    const float* gb  = (const float*)d_in[4];  // [8]
    const float* Uw  = (const float*)d_in[5];  // [8,384,64]
    const float* Ub  = (const float*)d_in[6];  // [8,64]
    const float* Vw  = (const float*)d_in[7];  // [8,384,64]
    const float* Vb  = (const float*)d_in[8];  // [8,64]
    float* out = (float*)d_out;                // [0:8192]=idx, [8192:16384]=logp, [16384]=aux

    const int SCORES_SMEM = 4096 * 8 + 64 * 64 * 4;   // 49152 B
    cudaFuncSetAttribute(k_scores, cudaFuncAttributeMaxDynamicSharedMemorySize, SCORES_SMEM);

    k_init   <<<(LIST_CAP + 255) / 256, 256>>>();
    k_gate   <<<BATCH / 8, 256>>>(x, gw, gb);
    k_offsets<<<1, 1>>>();
    k_scatter<<<NP / 256, 256>>>();
    k_ev     <<<RR * (EXP / TILE), 256>>>(re, Vw, Vb);
    k_xu     <<<N_TILES, 256>>>(x, Uw, Ub);
    k_scores <<<N_TILES, 256, SCORES_SMEM>>>();
    k_aux    <<<1, 256>>>(out);
    k_select <<<BATCH / 8, 256>>>(rnd, out);
}

// round 10
// speedup vs baseline: 1.4360x; 1.0944x over previous
#include <cuda_runtime.h>
#include <math.h>

#define BATCH 8192
#define EXP   1024
#define RR    8
#define DIM   384
#define HID   64
#define NP    (BATCH*2)             // 16384 (b,k) pairs
#define TILE  64                    // rows per tile (router-uniform)
#define LIST_CAP (NP + RR*TILE)     // 16896
#define N_TILES (LIST_CAP/TILE)     // 264

typedef unsigned long long u64;

// ---------------- f32x2 helpers (sm_103a packed fp32: 2x FMA throughput) ----------------
__device__ __forceinline__ u64 pack2(float lo, float hi) {
    u64 r; asm("mov.b64 %0, {%1, %2};" : "=l"(r) : "f"(lo), "f"(hi)); return r;
}
__device__ __forceinline__ float2 unpack2(u64 v) {
    float2 f; asm("mov.b64 {%0, %1}, %2;" : "=f"(f.x), "=f"(f.y) : "l"(v)); return f;
}
__device__ __forceinline__ void fma2(u64& d, u64 a, u64 b) {
    asm("fma.rn.f32x2 %0, %1, %2, %0;" : "+l"(d) : "l"(a), "l"(b));
}

// ---------------- device scratch ----------------
__device__ __align__(16) float g_probs[BATCH*RR];
__device__ int   g_top_idx[NP];
__device__ float g_top_gw[NP];
__device__ int   g_cnt[RR];
__device__ int   g_pos[RR];
__device__ int   g_list_bk[LIST_CAP];       // b*2+k, -1 = sentinel
__device__ float g_list_gw[LIST_CAP];
__device__ int   g_tile_r[N_TILES];         // router per 64-row tile, -1 = unused
__device__ __align__(16) float g_xu[LIST_CAP*HID];   // natural [row][h]
__device__ __align__(16) float g_ev[RR*EXP*HID];     // natural [r][e][h]
__device__ __align__(16) float g_contrib[NP*EXP];    // UNSCALED exp(score)
__device__ float g_scale[NP];               // gate_weight / sum_exp

// ---------------- kernel 1: init ----------------
__global__ void k_init() {
    int i = blockIdx.x * 256 + threadIdx.x;
    if (i < LIST_CAP) g_list_bk[i] = -1;
    if (i < N_TILES)  g_tile_r[i] = -1;
    if (i < RR)       g_cnt[i] = 0;
}

// ---------------- kernel 2: gate ----------------
__global__ __launch_bounds__(256) void k_gate(const float* __restrict__ x,
                                              const float* __restrict__ gw,
                                              const float* __restrict__ gb) {
    int w = threadIdx.x >> 5, lane = threadIdx.x & 31;
    int b = blockIdx.x * 8 + w;
    float acc[8];
#pragma unroll
    for (int r = 0; r < 8; r++) acc[r] = 0.f;
    const float* xr = x + b * DIM;
    for (int k = lane; k < DIM; k += 32) {
        float xv = xr[k];
        float4 a = *(const float4*)(gw + k * 8);
        float4 c = *(const float4*)(gw + k * 8 + 4);
        acc[0] = fmaf(xv, a.x, acc[0]); acc[1] = fmaf(xv, a.y, acc[1]);
        acc[2] = fmaf(xv, a.z, acc[2]); acc[3] = fmaf(xv, a.w, acc[3]);
        acc[4] = fmaf(xv, c.x, acc[4]); acc[5] = fmaf(xv, c.y, acc[5]);
        acc[6] = fmaf(xv, c.z, acc[6]); acc[7] = fmaf(xv, c.w, acc[7]);
    }
#pragma unroll
    for (int r = 0; r < 8; r++)
#pragma unroll
        for (int s = 16; s; s >>= 1) acc[r] += __shfl_xor_sync(0xffffffffu, acc[r], s);
    if (lane == 0) {
        float lg[8];
#pragma unroll
        for (int r = 0; r < 8; r++) lg[r] = acc[r] + gb[r];
        float m = lg[0];
#pragma unroll
        for (int r = 1; r < 8; r++) m = fmaxf(m, lg[r]);
        float s = 0.f, p[8];
#pragma unroll
        for (int r = 0; r < 8; r++) { p[r] = expf(lg[r] - m); s += p[r]; }
        float inv = 1.f / s;
#pragma unroll
        for (int r = 0; r < 8; r++) g_probs[b * 8 + r] = p[r] * inv;
        int i0 = 0;
#pragma unroll
        for (int r = 1; r < 8; r++) if (lg[r] > lg[i0]) i0 = r;
        int i1 = (i0 == 0) ? 1 : 0;
#pragma unroll
        for (int r = 0; r < 8; r++) if (r != i0 && r != i1 && lg[r] > lg[i1]) i1 = r;
        float e1 = expf(lg[i1] - lg[i0]);   // lg[i0] >= lg[i1]
        float d  = 1.f + e1;
        g_top_idx[b * 2 + 0] = i0; g_top_gw[b * 2 + 0] = 1.f / d;
        g_top_idx[b * 2 + 1] = i1; g_top_gw[b * 2 + 1] = e1 / d;
        atomicAdd(&g_cnt[i0], 1);
        atomicAdd(&g_cnt[i1], 1);
    }
}

// ---------------- kernel 3: padded bucket offsets + tile routers ----------------
__global__ void k_offsets() {
    int off = 0;
    for (int r = 0; r < RR; r++) {
        g_pos[r] = off;
        int pad = ((g_cnt[r] + TILE - 1) / TILE) * TILE;
        for (int tl = off / TILE; tl < (off + pad) / TILE; tl++) g_tile_r[tl] = r;
        off += pad;
    }
}

// ---------------- kernel 4: scatter (warp-aggregated atomics) ----------------
__global__ void k_scatter() {
    int tid = blockIdx.x * 256 + threadIdx.x;   // tid = b*2+k
    int lane = threadIdx.x & 31;
    int r = g_top_idx[tid];
    int p = 0;
#pragma unroll
    for (int rr = 0; rr < RR; rr++) {
        unsigned m = __ballot_sync(0xffffffffu, r == rr);
        if (r == rr) {
            int leader = __ffs(m) - 1;
            int basep = 0;
            if (lane == leader) basep = atomicAdd(&g_pos[rr], __popc(m));
            basep = __shfl_sync(m, basep, leader);
            p = basep + __popc(m & ((1u << lane) - 1u));
        }
    }
    g_list_bk[p] = tid;
    g_list_gw[p] = g_top_gw[tid];
}

// ---------------- shared GEMM body for xu/ev: 64 rows x 64 hid, K=384, f32x2 over d ----
// warp w owns rows 8w..8w+7; lane owns hid pair {lane, lane+32}.
// s_w: u64-swizzled [h][d2]: slot = h*32 + (d2 ^ (h&31)).
// inner loop over d4: x via LDS.128 broadcast (halves broadcast phases) ->
// per-SM per d4: crossbar 128 == FFMA2 128 (balanced, was 192:128).
template<bool IS_XU>
__device__ __forceinline__ void proj_body(const float* __restrict__ src,
                                          const float* __restrict__ Wb,
                                          const float* __restrict__ bias,
                                          const int* s_bk, int base, int e0,
                                          float* s_in, u64* s_w,
                                          float* dst) {
    int t = threadIdx.x, w = t >> 5, lane = t & 31;
    u64 acc[8][2];
#pragma unroll
    for (int i = 0; i < 8; i++) { acc[i][0] = 0ull; acc[i][1] = 0ull; }
    for (int c = 0; c < 6; c++) {
        __syncthreads();
#pragma unroll
        for (int i = 0; i < 4; i++) {          // stage 64 rows x 64 d (natural)
            int f = t + 256 * i, row = f >> 4, d16 = f & 15;
            float4 v = make_float4(0.f, 0.f, 0.f, 0.f);
            if (IS_XU) {
                int bk = s_bk[row];
                if (bk >= 0) v = *(const float4*)(src + (bk >> 1) * DIM + c * 64 + d16 * 4);
            } else {
                v = *(const float4*)(src + (e0 + row) * DIM + c * 64 + d16 * 4);
            }
            *(float4*)&s_in[row * 64 + d16 * 4] = v;
        }
        float* sw = (float*)s_w;
#pragma unroll
        for (int i = 0; i < 4; i++) {          // stage weights: transpose + swizzle
            int f = t + 256 * i, d = f >> 4, h16 = f & 15;
            float4 v = *(const float4*)(Wb + (c * 64 + d) * HID + h16 * 4);
            int d2 = d >> 1, par = d & 1;
            float vv[4] = {v.x, v.y, v.z, v.w};
#pragma unroll
            for (int jj = 0; jj < 4; jj++) {
                int h = h16 * 4 + jj;
                sw[(h * 32 + (d2 ^ (h & 31))) * 2 + par] = vv[jj];
            }
        }
        __syncthreads();
#pragma unroll 2
        for (int d4 = 0; d4 < 16; d4++) {
            int d2a = 2 * d4;
            u64 w00 = s_w[lane * 32 + (d2a ^ lane)];
            u64 w01 = s_w[lane * 32 + ((d2a + 1) ^ lane)];
            u64 w10 = s_w[(lane + 32) * 32 + (d2a ^ lane)];
            u64 w11 = s_w[(lane + 32) * 32 + ((d2a + 1) ^ lane)];
#pragma unroll
            for (int i = 0; i < 8; i++) {
                ulonglong2 xv = *(const ulonglong2*)&s_in[(8 * w + i) * 64 + 4 * d4]; // bcast
                fma2(acc[i][0], xv.x, w00); fma2(acc[i][0], xv.y, w01);
                fma2(acc[i][1], xv.x, w10); fma2(acc[i][1], xv.y, w11);
            }
        }
    }
    float b0 = bias[lane], b1 = bias[lane + 32];
#pragma unroll
    for (int i = 0; i < 8; i++) {
        float2 p0 = unpack2(acc[i][0]), p1 = unpack2(acc[i][1]);
        float y0 = p0.x + p0.y + b0;
        float y1 = p1.x + p1.y + b1;
        float ss = y0 * y0 + y1 * y1;
#pragma unroll
        for (int s = 16; s; s >>= 1) ss += __shfl_xor_sync(0xffffffffu, ss, s);
        float inv = 1.f / fmaxf(sqrtf(ss), 1e-12f);
        int row = base + 8 * w + i;
        dst[row * HID + lane]      = y0 * inv;
        dst[row * HID + lane + 32] = y1 * inv;
    }
}

// fused: blocks [0, N_TILES) do xu, [N_TILES, N_TILES+128) do ev
__global__ __launch_bounds__(256) void k_proj(const float* __restrict__ x,
                                              const float* __restrict__ Uw,
                                              const float* __restrict__ Ub,
                                              const float* __restrict__ re,
                                              const float* __restrict__ Vw,
                                              const float* __restrict__ Vb) {
    __shared__ float s_in[64 * 64];
    __shared__ u64   s_w[64 * 32];
    __shared__ int   s_bk[64];
    int t = threadIdx.x;
    if (blockIdx.x < N_TILES) {
        int r = g_tile_r[blockIdx.x];
        if (r < 0) return;
        int base = blockIdx.x * TILE;
        if (t < 64) s_bk[t] = g_list_bk[base + t];
        proj_body<true>(x, Uw + r * DIM * HID, Ub + r * HID, s_bk, base, 0, s_in, s_w, g_xu);
    } else {
        int bb = blockIdx.x - N_TILES;
        int r = bb >> 4, e0 = (bb & 15) * 64;   // 128 blocks: 16 tiles per router
        proj_body<false>(re, Vw + r * DIM * HID, Vb + r * HID, 0, r * EXP + e0, e0,
                         s_in, s_w, g_ev);
    }
}

// ---------------- kernel 7: scores GEMM + exp + per-row sum ----------------
// 64-row tile x 1024 experts, 8 chunks of 128 experts. warp w: rows 8w..8w+7;
// lane covers experts {lane, +32, +64, +96}. kk-packed f32x2.
// ev XOR-swizzled u64; staged with conflict-free STS.128 (u128 half-swap on odd e).
// xu via LDS.128 broadcast over kk4. Per chunk per CTA: crossbar 3072 < FFMA2 4096.
__global__ __launch_bounds__(256) void k_scores() {
    extern __shared__ u64 dyn[];
    u64*   s_ev = dyn;                      // 4096 u64 = 32 KB
    float* s_xu = (float*)(dyn + 4096);     // 16 KB
    __shared__ int   s_bk[64];
    __shared__ float s_gw[64];
    int t = threadIdx.x, w = t >> 5, lane = t & 31;
    int tile = blockIdx.x;
    int r = g_tile_r[tile];
    if (r < 0) return;
    int base = tile * TILE;
    if (t < 64) { s_bk[t] = g_list_bk[base + t]; s_gw[t] = g_list_gw[base + t]; }
#pragma unroll
    for (int i = 0; i < 4; i++)
        ((float4*)s_xu)[t + 256 * i] = ((const float4*)(g_xu + base * HID))[t + 256 * i];

    float rowsum[8];
#pragma unroll
    for (int i = 0; i < 8; i++) rowsum[i] = 0.f;

    const float* evb = g_ev + r * (EXP * HID);
    for (int c = 0; c < 8; c++) {
        __syncthreads();                    // covers s_xu/s_bk first iter, s_ev reuse later
#pragma unroll
        for (int i = 0; i < 8; i++) {       // stage 128 experts x 64 h, swizzled u128
            int f = t + 256 * i, e = f >> 4, k4 = f & 15;
            float4 v = *(const float4*)(evb + (c * 128 + e) * HID + k4 * 4);
            int s = e & 31;
            u64 lo = pack2(v.x, v.y), hi = pack2(v.z, v.w);
            // u64 slots (2k4)^s and (2k4+1)^s form an aligned u128; swap halves if s odd
            int base128 = e * 32 + (((2 * k4) ^ s) & ~1);
            ulonglong2 val;
            val.x = (s & 1) ? hi : lo;
            val.y = (s & 1) ? lo : hi;
            *(ulonglong2*)&s_ev[base128] = val;
        }
        __syncthreads();
        u64 acc[8][4];
#pragma unroll
        for (int i = 0; i < 8; i++)
#pragma unroll
            for (int j = 0; j < 4; j++) acc[i][j] = 0ull;
#pragma unroll 2
        for (int kk4 = 0; kk4 < 16; kk4++) {
            int k2a = 2 * kk4;
            u64 ea[4], eb[4];
#pragma unroll
            for (int j = 0; j < 4; j++) {   // e = j*32+lane -> swizzle key = lane
                ea[j] = s_ev[(j * 32 + lane) * 32 + (k2a ^ lane)];
                eb[j] = s_ev[(j * 32 + lane) * 32 + ((k2a + 1) ^ lane)];
            }
#pragma unroll
            for (int i = 0; i < 8; i++) {
                ulonglong2 xv = *(const ulonglong2*)&s_xu[(8 * w + i) * 64 + 4 * kk4]; // bcast
#pragma unroll
                for (int j = 0; j < 4; j++) {
                    fma2(acc[i][j], xv.x, ea[j]);
                    fma2(acc[i][j], xv.y, eb[j]);
                }
            }
        }
        // per-chunk epilogue: exp (|score|<=1, no max needed), unscaled write, run sums
#pragma unroll
        for (int i = 0; i < 8; i++) {
            int bk = s_bk[8 * w + i];
            float ex[4], loc = 0.f;
#pragma unroll
            for (int j = 0; j < 4; j++) {
                float2 p = unpack2(acc[i][j]);
                ex[j] = __expf(p.x + p.y);
                loc += ex[j];
            }
            rowsum[i] += loc;
            if (bk >= 0) {
                float* o = g_contrib + bk * EXP + c * 128;
#pragma unroll
                for (int j = 0; j < 4; j++) o[j * 32 + lane] = ex[j];
            }
        }
    }
#pragma unroll
    for (int i = 0; i < 8; i++) {
        float s = rowsum[i];
#pragma unroll
        for (int st = 16; st; st >>= 1) s += __shfl_xor_sync(0xffffffffu, s, st);
        int row = 8 * w + i;
        int bk = s_bk[row];
        if (lane == 0 && bk >= 0) g_scale[bk] = s_gw[row] / s;
    }
}

// ---------------- kernel 8: select (inverse-CDF) + aux loss (last block) ----------------
__global__ __launch_bounds__(256) void k_select_aux(const float* __restrict__ rnd,
                                                    float* __restrict__ out) {
    __shared__ float sp[256][8];
    __shared__ float sm[256][8];
    int t = threadIdx.x;
    if (blockIdx.x == BATCH / 8) {          // aux block
        float p[8], mk[8];
#pragma unroll
        for (int r = 0; r < 8; r++) { p[r] = 0.f; mk[r] = 0.f; }
        for (int b = t; b < BATCH; b += 256) {
#pragma unroll
            for (int r = 0; r < 8; r++) p[r] += g_probs[b * 8 + r];
            int i0 = g_top_idx[b * 2], i1 = g_top_idx[b * 2 + 1];
#pragma unroll
            for (int r = 0; r < 8; r++) mk[r] += (r == i0 ? 1.f : 0.f) + (r == i1 ? 1.f : 0.f);
        }
#pragma unroll
        for (int r = 0; r < 8; r++) { sp[t][r] = p[r]; sm[t][r] = mk[r]; }
        __syncthreads();
        for (int s = 128; s; s >>= 1) {
            if (t < s)
#pragma unroll
                for (int r = 0; r < 8; r++) { sp[t][r] += sp[t + s][r]; sm[t][r] += sm[t + s][r]; }
            __syncthreads();
        }
        if (t == 0) {
            float a = 0.f;
#pragma unroll
            for (int r = 0; r < 8; r++)
                a += (sp[0][r] / (float)BATCH) * (sm[0][r] / (float)BATCH);
            out[2 * BATCH] = 8.f * a * 0.05f;
        }
        return;
    }
    int w = t >> 5, lane = t & 31;
    int b = blockIdx.x * 8 + w;
    float rn = rnd[b];
    float s0 = g_scale[b * 2], s1 = g_scale[b * 2 + 1];
    const float* c0 = g_contrib + (b * 2) * EXP;
    const float* c1 = c0 + EXP;
    float run = 0.f;
    int sel = -1;
    for (int c = 0; c < 32; c++) {
        int e = c * 32 + lane;
        float v = c0[e] * s0 + c1[e] * s1;
        float s = v;
#pragma unroll
        for (int st = 1; st < 32; st <<= 1) {
            float o = __shfl_up_sync(0xffffffffu, s, st);
            if (lane >= st) s += o;
        }
        float cum = run + s;
        unsigned mask = __ballot_sync(0xffffffffu, cum > rn);
        if (mask) { sel = c * 32 + __ffs(mask) - 1; break; }
        run += __shfl_sync(0xffffffffu, s, 31);
    }
    if (sel < 0) sel = 0;
    if (lane == 0) {
        float pv = c0[sel] * s0 + c1[sel] * s1;
        out[b] = (float)sel;
        out[BATCH + b] = logf(pv);
    }
}

// ---------------- launch ----------------
extern "C" void kernel_launch(void* const* d_in, const int* in_sizes, int n_in,
                              void* d_out, int out_size) {
    const float* x   = (const float*)d_in[0];  // [8192,384]
    const float* re  = (const float*)d_in[1];  // [1024,384]
    const float* rnd = (const float*)d_in[2];  // [8192,1]
    const float* gw  = (const float*)d_in[3];  // [384,8]
    const float* gb  = (const float*)d_in[4];  // [8]
    const float* Uw  = (const float*)d_in[5];  // [8,384,64]
    const float* Ub  = (const float*)d_in[6];  // [8,64]
    const float* Vw  = (const float*)d_in[7];  // [8,384,64]
    const float* Vb  = (const float*)d_in[8];  // [8,64]
    float* out = (float*)d_out;                // [0:8192]=idx, [8192:16384]=logp, [16384]=aux

    const int SCORES_SMEM = 4096 * 8 + 64 * 64 * 4;   // 49152 B
    cudaFuncSetAttribute(k_scores, cudaFuncAttributeMaxDynamicSharedMemorySize, SCORES_SMEM);

    k_init      <<<(LIST_CAP + 255) / 256, 256>>>();
    k_gate      <<<BATCH / 8, 256>>>(x, gw, gb);
    k_offsets   <<<1, 1>>>();
    k_scatter   <<<NP / 256, 256>>>();
    k_proj      <<<N_TILES + RR * (EXP / TILE), 256>>>(x, Uw, Ub, re, Vw, Vb);
    k_scores    <<<N_TILES, 256, SCORES_SMEM>>>();
    k_select_aux<<<BATCH / 8 + 1, 256>>>(rnd, out);
}